// round 9
// baseline (speedup 1.0000x reference)
#include <cuda_runtime.h>
#include <math.h>
#include <stdint.h>

// ---------------------------------------------------------------------------
// Problem constants
// ---------------------------------------------------------------------------
#define B_SZ    2
#define S_LEN   2048
#define D_MODEL 1024
#define N_HEADS 16
#define D_HEAD  64
#define M_ROWS  (B_SZ * S_LEN)          // 4096

// ---------------------------------------------------------------------------
// Scratch (device globals: allocation-free)
// g_Q/g_K/g_V: [B, H, S, 64] fp32   g_Ctx: [B*S, 1024] fp32
// ---------------------------------------------------------------------------
__device__ float g_Q[B_SZ * N_HEADS * S_LEN * D_HEAD];
__device__ float g_K[B_SZ * N_HEADS * S_LEN * D_HEAD];
__device__ float g_V[B_SZ * N_HEADS * S_LEN * D_HEAD];
__device__ float g_Ctx[M_ROWS * D_MODEL];

// ---------------------------------------------------------------------------
// SGEMM: C = (A[MxK] @ W[KxN] + bias) * scale
//   qkv==1: scatter to [B,H,S,64] layout (n -> (h,d))
//   qkv==0: row-major [M,N]
// Block tile 128x128, K-step 8, 256 threads, 8x8 per thread.
// ---------------------------------------------------------------------------
__global__ __launch_bounds__(256, 2)
void sgemm128x128(const float* __restrict__ A, const float* __restrict__ W,
                  const float* __restrict__ bias, float* __restrict__ C,
                  int M, int N, int K, int qkv, float scale)
{
    __shared__ float As[8][128];   // transposed A tile: As[k][m]
    __shared__ float Ws[8][128];   // Ws[k][n]

    const int tid = threadIdx.x;
    const int tx  = tid & 15;      // 0..15 -> col group (8 cols)
    const int ty  = tid >> 4;      // 0..15 -> row group (8 rows)

    const int mBase = blockIdx.y * 128;
    const int nBase = blockIdx.x * 128;

    const int arow = tid >> 1;           // 0..127
    const int acol = (tid & 1) * 4;      // 0 or 4
    const int wrow = tid >> 5;           // 0..7
    const int wcol = (tid & 31) * 4;     // 0..124

    float acc[8][8];
#pragma unroll
    for (int i = 0; i < 8; i++)
#pragma unroll
        for (int j = 0; j < 8; j++) acc[i][j] = 0.f;

    for (int k0 = 0; k0 < K; k0 += 8) {
        // global fetch (before sync, overlaps with previous compute tail)
        float4 av = *(const float4*)(A + (size_t)(mBase + arow) * K + k0 + acol);
        float4 wv = *(const float4*)(W + (size_t)(k0 + wrow) * N + nBase + wcol);
        __syncthreads();
        As[acol + 0][arow] = av.x;
        As[acol + 1][arow] = av.y;
        As[acol + 2][arow] = av.z;
        As[acol + 3][arow] = av.w;
        *(float4*)(&Ws[wrow][wcol]) = wv;
        __syncthreads();

#pragma unroll
        for (int k = 0; k < 8; k++) {
            float4 a0 = *(const float4*)(&As[k][ty * 8]);
            float4 a1 = *(const float4*)(&As[k][ty * 8 + 4]);
            float4 b0 = *(const float4*)(&Ws[k][tx * 8]);
            float4 b1 = *(const float4*)(&Ws[k][tx * 8 + 4]);
            float ar[8] = {a0.x, a0.y, a0.z, a0.w, a1.x, a1.y, a1.z, a1.w};
            float br[8] = {b0.x, b0.y, b0.z, b0.w, b1.x, b1.y, b1.z, b1.w};
#pragma unroll
            for (int i = 0; i < 8; i++)
#pragma unroll
                for (int j = 0; j < 8; j++)
                    acc[i][j] += ar[i] * br[j];
        }
    }

    // epilogue
#pragma unroll
    for (int i = 0; i < 8; i++) {
        const int m  = mBase + ty * 8 + i;
        const int b_ = m >> 11;          // / S_LEN
        const int s_ = m & (S_LEN - 1);
#pragma unroll
        for (int j = 0; j < 8; j++) {
            const int n = nBase + tx * 8 + j;
            float v = acc[i][j];
            if (bias) v += bias[n];
            v *= scale;
            if (qkv) {
                const int hh = n >> 6;
                const int dd = n & 63;
                C[((((size_t)(b_ * N_HEADS + hh)) * S_LEN + s_) << 6) + dd] = v;
            } else {
                C[(size_t)m * N + n] = v;
            }
        }
    }
}

// ---------------------------------------------------------------------------
// Flash attention (causal). One block per (q-tile 64, b*h).
// 128 threads: ty=tid>>4 (8 groups x 8 rows), tx=tid&15 (16 groups x 4 cols).
// smem: Qs[64][68], KPs[64][68] (K tile, later reused for P), Vs[64][68].
// ---------------------------------------------------------------------------
#define SM_STRIDE 68
#define ATTN_SMEM (3 * 64 * SM_STRIDE * 4)
#define NEG_INF   (-1e30f)

__global__ __launch_bounds__(128)
void attn_kernel(const float* __restrict__ gQ, const float* __restrict__ gK,
                 const float* __restrict__ gV, float* __restrict__ gO)
{
    const int qt = gridDim.x - 1 - blockIdx.x;   // reversed: heavy blocks first
    const int bh = blockIdx.y;
    const int b  = bh >> 4;
    const int h  = bh & 15;

    extern __shared__ float sm[];
    float* Qs  = sm;
    float* KPs = sm + 64 * SM_STRIDE;
    float* Vs  = sm + 2 * 64 * SM_STRIDE;

    const int tid = threadIdx.x;
    const int tx  = tid & 15;
    const int ty  = tid >> 4;
    const int r0  = ty * 8;
    const int c0  = tx * 4;

    // load Q tile [64 x 64] -> Qs[r][d]
    const float* Qbase = gQ + ((size_t)bh * S_LEN + qt * 64) * D_HEAD;
    for (int it = tid; it < 64 * 16; it += 128) {
        const int r  = it >> 4;
        const int d4 = (it & 15) * 4;
        *(float4*)(Qs + r * SM_STRIDE + d4) =
            *(const float4*)(Qbase + r * D_HEAD + d4);
    }

    float m_i[8], l_i[8], acc[8][4];
#pragma unroll
    for (int i = 0; i < 8; i++) {
        m_i[i] = NEG_INF;
        l_i[i] = 0.f;
#pragma unroll
        for (int j = 0; j < 4; j++) acc[i][j] = 0.f;
    }

    const float* Kbase = gK + (size_t)bh * S_LEN * D_HEAD;
    const float* Vbase = gV + (size_t)bh * S_LEN * D_HEAD;

    for (int jt = 0; jt <= qt; ++jt) {
        __syncthreads();   // Q visible (1st iter) / prev PV reads done

        const float* Kt = Kbase + (size_t)(jt * 64) * D_HEAD;
        const float* Vt = Vbase + (size_t)(jt * 64) * D_HEAD;
        for (int it = tid; it < 64 * 16; it += 128) {
            const int r  = it >> 4;
            const int d4 = (it & 15) * 4;
            *(float4*)(KPs + r * SM_STRIDE + d4) = *(const float4*)(Kt + r * D_HEAD + d4);
            *(float4*)(Vs  + r * SM_STRIDE + d4) = *(const float4*)(Vt + r * D_HEAD + d4);
        }
        __syncthreads();

        // scores s[i][j] = Q[r0+i,:] . K[c0+j,:]   (Q already pre-scaled)
        float s[8][4];
#pragma unroll
        for (int i = 0; i < 8; i++)
#pragma unroll
            for (int j = 0; j < 4; j++) s[i][j] = 0.f;

#pragma unroll
        for (int k4 = 0; k4 < 16; ++k4) {
            float4 kv[4];
#pragma unroll
            for (int j = 0; j < 4; j++)
                kv[j] = *(const float4*)(KPs + (c0 + j) * SM_STRIDE + k4 * 4);
#pragma unroll
            for (int i = 0; i < 8; i++) {
                float4 qv = *(const float4*)(Qs + (r0 + i) * SM_STRIDE + k4 * 4);
#pragma unroll
                for (int j = 0; j < 4; j++)
                    s[i][j] += qv.x * kv[j].x + qv.y * kv[j].y +
                               qv.z * kv[j].z + qv.w * kv[j].w;
            }
        }

        // causal mask (only the diagonal tile)
        if (jt == qt) {
#pragma unroll
            for (int i = 0; i < 8; i++)
#pragma unroll
                for (int j = 0; j < 4; j++)
                    if (c0 + j > r0 + i) s[i][j] = NEG_INF;
        }

        // online softmax update (row reduction over 16-lane tx group)
#pragma unroll
        for (int i = 0; i < 8; i++) {
            float mx = fmaxf(fmaxf(s[i][0], s[i][1]), fmaxf(s[i][2], s[i][3]));
#pragma unroll
            for (int off = 8; off >= 1; off >>= 1)
                mx = fmaxf(mx, __shfl_xor_sync(0xffffffffu, mx, off));
            const float mn = fmaxf(m_i[i], mx);
            const float f  = __expf(m_i[i] - mn);
            float rs = 0.f;
#pragma unroll
            for (int j = 0; j < 4; j++) {
                s[i][j] = __expf(s[i][j] - mn);
                rs += s[i][j];
            }
#pragma unroll
            for (int off = 8; off >= 1; off >>= 1)
                rs += __shfl_xor_sync(0xffffffffu, rs, off);
            l_i[i] = l_i[i] * f + rs;
            m_i[i] = mn;
#pragma unroll
            for (int j = 0; j < 4; j++) acc[i][j] *= f;
        }

        // write P over the (dead) K tile: P[qrow][kvcol]
        __syncthreads();
#pragma unroll
        for (int i = 0; i < 8; i++)
            *(float4*)(KPs + (r0 + i) * SM_STRIDE + c0) =
                make_float4(s[i][0], s[i][1], s[i][2], s[i][3]);
        __syncthreads();

        // acc += P @ V   (contraction over the 64 kv rows)
#pragma unroll
        for (int k4 = 0; k4 < 16; ++k4) {
            float4 vv[4];
#pragma unroll
            for (int kk = 0; kk < 4; kk++)
                vv[kk] = *(const float4*)(Vs + (k4 * 4 + kk) * SM_STRIDE + c0);
#pragma unroll
            for (int i = 0; i < 8; i++) {
                float4 pv = *(const float4*)(KPs + (r0 + i) * SM_STRIDE + k4 * 4);
                acc[i][0] += pv.x * vv[0].x + pv.y * vv[1].x + pv.z * vv[2].x + pv.w * vv[3].x;
                acc[i][1] += pv.x * vv[0].y + pv.y * vv[1].y + pv.z * vv[2].y + pv.w * vv[3].y;
                acc[i][2] += pv.x * vv[0].z + pv.y * vv[1].z + pv.z * vv[2].z + pv.w * vv[3].z;
                acc[i][3] += pv.x * vv[0].w + pv.y * vv[1].w + pv.z * vv[2].w + pv.w * vv[3].w;
            }
        }
    }

    // epilogue: ctx[b, qrow, h*64 + c] = acc / l
    const size_t orow = (size_t)b * S_LEN + (size_t)qt * 64;
#pragma unroll
    for (int i = 0; i < 8; i++) {
        const float inv = 1.0f / l_i[i];
        float* dst = gO + (orow + r0 + i) * D_MODEL + h * 64 + c0;
        *(float4*)dst = make_float4(acc[i][0] * inv, acc[i][1] * inv,
                                    acc[i][2] * inv, acc[i][3] * inv);
    }
}

// ---------------------------------------------------------------------------
// kernel_launch
// inputs: x, Wq, bq, Wk, bk, Wv, bv, Wo  (all fp32)
// ---------------------------------------------------------------------------
extern "C" void kernel_launch(void* const* d_in, const int* in_sizes, int n_in,
                              void* d_out, int out_size)
{
    const float* x  = (const float*)d_in[0];
    const float* Wq = (const float*)d_in[1];
    const float* bq = (const float*)d_in[2];
    const float* Wk = (const float*)d_in[3];
    const float* bk = (const float*)d_in[4];
    const float* Wv = (const float*)d_in[5];
    const float* bv = (const float*)d_in[6];
    const float* Wo = (const float*)d_in[7];
    float* out = (float*)d_out;

    float *pQ, *pK, *pV, *pCtx;
    cudaGetSymbolAddress((void**)&pQ,   g_Q);
    cudaGetSymbolAddress((void**)&pK,   g_K);
    cudaGetSymbolAddress((void**)&pV,   g_V);
    cudaGetSymbolAddress((void**)&pCtx, g_Ctx);

    cudaFuncSetAttribute(attn_kernel,
                         cudaFuncAttributeMaxDynamicSharedMemorySize, ATTN_SMEM);

    dim3 gg(D_MODEL / 128, M_ROWS / 128);   // (8, 32)
    dim3 gt(256);

    // QKV projections (Q pre-scaled by 1/sqrt(64) = 0.125)
    sgemm128x128<<<gg, gt>>>(x, Wq, bq, pQ, M_ROWS, D_MODEL, D_MODEL, 1, 0.125f);
    sgemm128x128<<<gg, gt>>>(x, Wk, bk, pK, M_ROWS, D_MODEL, D_MODEL, 1, 1.0f);
    sgemm128x128<<<gg, gt>>>(x, Wv, bv, pV, M_ROWS, D_MODEL, D_MODEL, 1, 1.0f);

    // flash attention: 32 q-tiles x 32 (b*h)
    attn_kernel<<<dim3(S_LEN / 64, B_SZ * N_HEADS), 128, ATTN_SMEM>>>(pQ, pK, pV, pCtx);

    // output projection
    sgemm128x128<<<gg, gt>>>(pCtx, Wo, nullptr, out, M_ROWS, D_MODEL, D_MODEL, 0, 1.0f);
}

// round 10
// speedup vs baseline: 1.0060x; 1.0060x over previous
#include <cuda_runtime.h>
#include <math.h>
#include <stdint.h>

// ---------------------------------------------------------------------------
// Problem constants
// ---------------------------------------------------------------------------
#define B_SZ    2
#define S_LEN   2048
#define D_MODEL 1024
#define N_HEADS 16
#define D_HEAD  64
#define M_ROWS  (B_SZ * S_LEN)          // 4096

// ---------------------------------------------------------------------------
// Scratch (device globals: allocation-free)
// g_Q/g_K/g_V: [B, H, S, 64] fp32   g_Ctx: [B*S, 1024] fp32
// ---------------------------------------------------------------------------
__device__ float g_Q[B_SZ * N_HEADS * S_LEN * D_HEAD];
__device__ float g_K[B_SZ * N_HEADS * S_LEN * D_HEAD];
__device__ float g_V[B_SZ * N_HEADS * S_LEN * D_HEAD];
__device__ float g_Ctx[M_ROWS * D_MODEL];

// ---------------------------------------------------------------------------
// SGEMM: C = (A[MxK] @ W[KxN] + bias) * scale
//   qkv==1: scatter to [B,H,S,64] layout (n -> (h,d))
//   qkv==0: row-major [M,N]
// Block tile 128x128, K-step 8, 256 threads, 8x8 per thread.
// ---------------------------------------------------------------------------
__global__ __launch_bounds__(256, 2)
void sgemm128x128(const float* __restrict__ A, const float* __restrict__ W,
                  const float* __restrict__ bias, float* __restrict__ C,
                  int M, int N, int K, int qkv, float scale)
{
    __shared__ float As[8][128];   // transposed A tile: As[k][m]
    __shared__ float Ws[8][128];   // Ws[k][n]

    const int tid = threadIdx.x;
    const int tx  = tid & 15;      // 0..15 -> col group (8 cols)
    const int ty  = tid >> 4;      // 0..15 -> row group (8 rows)

    const int mBase = blockIdx.y * 128;
    const int nBase = blockIdx.x * 128;

    const int arow = tid >> 1;           // 0..127
    const int acol = (tid & 1) * 4;      // 0 or 4
    const int wrow = tid >> 5;           // 0..7
    const int wcol = (tid & 31) * 4;     // 0..124

    float acc[8][8];
#pragma unroll
    for (int i = 0; i < 8; i++)
#pragma unroll
        for (int j = 0; j < 8; j++) acc[i][j] = 0.f;

    for (int k0 = 0; k0 < K; k0 += 8) {
        // global fetch (before sync, overlaps with previous compute tail)
        float4 av = *(const float4*)(A + (size_t)(mBase + arow) * K + k0 + acol);
        float4 wv = *(const float4*)(W + (size_t)(k0 + wrow) * N + nBase + wcol);
        __syncthreads();
        As[acol + 0][arow] = av.x;
        As[acol + 1][arow] = av.y;
        As[acol + 2][arow] = av.z;
        As[acol + 3][arow] = av.w;
        *(float4*)(&Ws[wrow][wcol]) = wv;
        __syncthreads();

#pragma unroll
        for (int k = 0; k < 8; k++) {
            float4 a0 = *(const float4*)(&As[k][ty * 8]);
            float4 a1 = *(const float4*)(&As[k][ty * 8 + 4]);
            float4 b0 = *(const float4*)(&Ws[k][tx * 8]);
            float4 b1 = *(const float4*)(&Ws[k][tx * 8 + 4]);
            float ar[8] = {a0.x, a0.y, a0.z, a0.w, a1.x, a1.y, a1.z, a1.w};
            float br[8] = {b0.x, b0.y, b0.z, b0.w, b1.x, b1.y, b1.z, b1.w};
#pragma unroll
            for (int i = 0; i < 8; i++)
#pragma unroll
                for (int j = 0; j < 8; j++)
                    acc[i][j] += ar[i] * br[j];
        }
    }

    // epilogue
#pragma unroll
    for (int i = 0; i < 8; i++) {
        const int m  = mBase + ty * 8 + i;
        const int b_ = m >> 11;          // / S_LEN
        const int s_ = m & (S_LEN - 1);
#pragma unroll
        for (int j = 0; j < 8; j++) {
            const int n = nBase + tx * 8 + j;
            float v = acc[i][j];
            if (bias) v += bias[n];
            v *= scale;
            if (qkv) {
                const int hh = n >> 6;
                const int dd = n & 63;
                C[((((size_t)(b_ * N_HEADS + hh)) * S_LEN + s_) << 6) + dd] = v;
            } else {
                C[(size_t)m * N + n] = v;
            }
        }
    }
}

// ---------------------------------------------------------------------------
// Flash attention (causal). One block per (q-tile 64, b*h).
// 128 threads: ty=tid>>4 (8 groups x 8 rows), tx=tid&15 (16 groups x 4 cols).
// smem: Qs[64][68], KPs[64][68] (K tile, later reused for P), Vs[64][68].
// ---------------------------------------------------------------------------
#define SM_STRIDE 68
#define ATTN_SMEM (3 * 64 * SM_STRIDE * 4)
#define NEG_INF   (-1e30f)

__global__ __launch_bounds__(128)
void attn_kernel(const float* __restrict__ gQ, const float* __restrict__ gK,
                 const float* __restrict__ gV, float* __restrict__ gO)
{
    const int qt = gridDim.x - 1 - blockIdx.x;   // reversed: heavy blocks first
    const int bh = blockIdx.y;
    const int b  = bh >> 4;
    const int h  = bh & 15;

    extern __shared__ float sm[];
    float* Qs  = sm;
    float* KPs = sm + 64 * SM_STRIDE;
    float* Vs  = sm + 2 * 64 * SM_STRIDE;

    const int tid = threadIdx.x;
    const int tx  = tid & 15;
    const int ty  = tid >> 4;
    const int r0  = ty * 8;
    const int c0  = tx * 4;

    // load Q tile [64 x 64] -> Qs[r][d]
    const float* Qbase = gQ + ((size_t)bh * S_LEN + qt * 64) * D_HEAD;
    for (int it = tid; it < 64 * 16; it += 128) {
        const int r  = it >> 4;
        const int d4 = (it & 15) * 4;
        *(float4*)(Qs + r * SM_STRIDE + d4) =
            *(const float4*)(Qbase + r * D_HEAD + d4);
    }

    float m_i[8], l_i[8], acc[8][4];
#pragma unroll
    for (int i = 0; i < 8; i++) {
        m_i[i] = NEG_INF;
        l_i[i] = 0.f;
#pragma unroll
        for (int j = 0; j < 4; j++) acc[i][j] = 0.f;
    }

    const float* Kbase = gK + (size_t)bh * S_LEN * D_HEAD;
    const float* Vbase = gV + (size_t)bh * S_LEN * D_HEAD;

    for (int jt = 0; jt <= qt; ++jt) {
        __syncthreads();   // Q visible (1st iter) / prev PV reads done

        const float* Kt = Kbase + (size_t)(jt * 64) * D_HEAD;
        const float* Vt = Vbase + (size_t)(jt * 64) * D_HEAD;
        for (int it = tid; it < 64 * 16; it += 128) {
            const int r  = it >> 4;
            const int d4 = (it & 15) * 4;
            *(float4*)(KPs + r * SM_STRIDE + d4) = *(const float4*)(Kt + r * D_HEAD + d4);
            *(float4*)(Vs  + r * SM_STRIDE + d4) = *(const float4*)(Vt + r * D_HEAD + d4);
        }
        __syncthreads();

        // scores s[i][j] = Q[r0+i,:] . K[c0+j,:]   (Q already pre-scaled)
        float s[8][4];
#pragma unroll
        for (int i = 0; i < 8; i++)
#pragma unroll
            for (int j = 0; j < 4; j++) s[i][j] = 0.f;

#pragma unroll
        for (int k4 = 0; k4 < 16; ++k4) {
            float4 kv[4];
#pragma unroll
            for (int j = 0; j < 4; j++)
                kv[j] = *(const float4*)(KPs + (c0 + j) * SM_STRIDE + k4 * 4);
#pragma unroll
            for (int i = 0; i < 8; i++) {
                float4 qv = *(const float4*)(Qs + (r0 + i) * SM_STRIDE + k4 * 4);
#pragma unroll
                for (int j = 0; j < 4; j++)
                    s[i][j] += qv.x * kv[j].x + qv.y * kv[j].y +
                               qv.z * kv[j].z + qv.w * kv[j].w;
            }
        }

        // causal mask (only the diagonal tile)
        if (jt == qt) {
#pragma unroll
            for (int i = 0; i < 8; i++)
#pragma unroll
                for (int j = 0; j < 4; j++)
                    if (c0 + j > r0 + i) s[i][j] = NEG_INF;
        }

        // online softmax update (row reduction over 16-lane tx group)
#pragma unroll
        for (int i = 0; i < 8; i++) {
            float mx = fmaxf(fmaxf(s[i][0], s[i][1]), fmaxf(s[i][2], s[i][3]));
#pragma unroll
            for (int off = 8; off >= 1; off >>= 1)
                mx = fmaxf(mx, __shfl_xor_sync(0xffffffffu, mx, off));
            const float mn = fmaxf(m_i[i], mx);
            const float f  = __expf(m_i[i] - mn);
            float rs = 0.f;
#pragma unroll
            for (int j = 0; j < 4; j++) {
                s[i][j] = __expf(s[i][j] - mn);
                rs += s[i][j];
            }
#pragma unroll
            for (int off = 8; off >= 1; off >>= 1)
                rs += __shfl_xor_sync(0xffffffffu, rs, off);
            l_i[i] = l_i[i] * f + rs;
            m_i[i] = mn;
#pragma unroll
            for (int j = 0; j < 4; j++) acc[i][j] *= f;
        }

        // write P over the (dead) K tile: P[qrow][kvcol]
        __syncthreads();
#pragma unroll
        for (int i = 0; i < 8; i++)
            *(float4*)(KPs + (r0 + i) * SM_STRIDE + c0) =
                make_float4(s[i][0], s[i][1], s[i][2], s[i][3]);
        __syncthreads();

        // acc += P @ V   (contraction over the 64 kv rows)
#pragma unroll
        for (int k4 = 0; k4 < 16; ++k4) {
            float4 vv[4];
#pragma unroll
            for (int kk = 0; kk < 4; kk++)
                vv[kk] = *(const float4*)(Vs + (k4 * 4 + kk) * SM_STRIDE + c0);
#pragma unroll
            for (int i = 0; i < 8; i++) {
                float4 pv = *(const float4*)(KPs + (r0 + i) * SM_STRIDE + k4 * 4);
                acc[i][0] += pv.x * vv[0].x + pv.y * vv[1].x + pv.z * vv[2].x + pv.w * vv[3].x;
                acc[i][1] += pv.x * vv[0].y + pv.y * vv[1].y + pv.z * vv[2].y + pv.w * vv[3].y;
                acc[i][2] += pv.x * vv[0].z + pv.y * vv[1].z + pv.z * vv[2].z + pv.w * vv[3].z;
                acc[i][3] += pv.x * vv[0].w + pv.y * vv[1].w + pv.z * vv[2].w + pv.w * vv[3].w;
            }
        }
    }

    // epilogue: ctx[b, qrow, h*64 + c] = acc / l
    const size_t orow = (size_t)b * S_LEN + (size_t)qt * 64;
#pragma unroll
    for (int i = 0; i < 8; i++) {
        const float inv = 1.0f / l_i[i];
        float* dst = gO + (orow + r0 + i) * D_MODEL + h * 64 + c0;
        *(float4*)dst = make_float4(acc[i][0] * inv, acc[i][1] * inv,
                                    acc[i][2] * inv, acc[i][3] * inv);
    }
}

// ---------------------------------------------------------------------------
// kernel_launch
// inputs: x, Wq, bq, Wk, bk, Wv, bv, Wo  (all fp32)
// ---------------------------------------------------------------------------
extern "C" void kernel_launch(void* const* d_in, const int* in_sizes, int n_in,
                              void* d_out, int out_size)
{
    const float* x  = (const float*)d_in[0];
    const float* Wq = (const float*)d_in[1];
    const float* bq = (const float*)d_in[2];
    const float* Wk = (const float*)d_in[3];
    const float* bk = (const float*)d_in[4];
    const float* Wv = (const float*)d_in[5];
    const float* bv = (const float*)d_in[6];
    const float* Wo = (const float*)d_in[7];
    float* out = (float*)d_out;

    float *pQ, *pK, *pV, *pCtx;
    cudaGetSymbolAddress((void**)&pQ,   g_Q);
    cudaGetSymbolAddress((void**)&pK,   g_K);
    cudaGetSymbolAddress((void**)&pV,   g_V);
    cudaGetSymbolAddress((void**)&pCtx, g_Ctx);

    cudaFuncSetAttribute(attn_kernel,
                         cudaFuncAttributeMaxDynamicSharedMemorySize, ATTN_SMEM);

    dim3 gg(D_MODEL / 128, M_ROWS / 128);   // (8, 32)
    dim3 gt(256);

    // QKV projections (Q pre-scaled by 1/sqrt(64) = 0.125)
    sgemm128x128<<<gg, gt>>>(x, Wq, bq, pQ, M_ROWS, D_MODEL, D_MODEL, 1, 0.125f);
    sgemm128x128<<<gg, gt>>>(x, Wk, bk, pK, M_ROWS, D_MODEL, D_MODEL, 1, 1.0f);
    sgemm128x128<<<gg, gt>>>(x, Wv, bv, pV, M_ROWS, D_MODEL, D_MODEL, 1, 1.0f);

    // flash attention: 32 q-tiles x 32 (b*h)
    attn_kernel<<<dim3(S_LEN / 64, B_SZ * N_HEADS), 128, ATTN_SMEM>>>(pQ, pK, pV, pCtx);

    // output projection
    sgemm128x128<<<gg, gt>>>(pCtx, Wo, nullptr, out, M_ROWS, D_MODEL, D_MODEL, 0, 1.0f);
}